// round 13
// baseline (speedup 1.0000x reference)
#include <cuda_runtime.h>
#include <cuda_fp16.h>
#include <stdint.h>
#include <stddef.h>

// ---------------------------------------------------------------------------
// out0 = normalize_rows(x) @ features^T   [2048 x 100000]  (fp32)
// out1 = features (passthrough)           [100000 x 256]
// Round 12: SMEM-FREE mainloop. Prep writes A and B in MMA fragment order;
// GEMM loads fragments with coalesced LDG.128 directly into registers.
// No ldmatrix, no STS, no barriers -> smem port freed for nothing (unused).
// ---------------------------------------------------------------------------

#define MROWS 2048
#define KDIM  256
#define NPAD  100096      // 782 * 128
#define MT    16          // m tiles
#define NT    782         // n tiles

#define BM 128
#define BN 128
#define NCHUNK 4
#define NKS 4             // k-steps per chunk (k16 each)

// A fragments: [mt][chunk][ks][mfrag(8)] -> 32 lanes x 16B (= full m16k16 frag)
// B frag-pairs: [nt][chunk][ks][nfp(8)]  -> 32 lanes x 16B (= two n8k16 frags)
__device__ __align__(1024) uint4 g_Ap[(size_t)MT * NCHUNK * NKS * 8 * 32];
__device__ __align__(1024) uint4 g_Bp[(size_t)NT * NCHUNK * NKS * 8 * 32];

// ------------------------------ helpers -----------------------------------

#define MMA(c, a, b0v, b1v)                                                   \
    asm volatile(                                                             \
        "mma.sync.aligned.m16n8k16.row.col.f32.f16.f16.f32 "                  \
        "{%0,%1,%2,%3},{%4,%5,%6,%7},{%8,%9},{%0,%1,%2,%3};"                  \
        : "+f"((c)[0]), "+f"((c)[1]), "+f"((c)[2]), "+f"((c)[3])              \
        : "r"((a).x), "r"((a).y), "r"((a).z), "r"((a).w),                     \
          "r"(b0v), "r"(b1v))

// --------------------------- prep kernels ---------------------------------

// Normalize rows of x and scatter into fragment-ordered g_Ap.
// 8 warps per block, one warp per row.
__global__ void normA_kernel(const float* __restrict__ x) {
    int row = blockIdx.x * 8 + ((int)threadIdx.x >> 5);
    int t = threadIdx.x & 31;               // owns k = 8t .. 8t+7
    const float4* xr = (const float4*)(x + (size_t)row * KDIM);
    float4 v0 = xr[2 * t], v1 = xr[2 * t + 1];
    float s = v0.x * v0.x + v0.y * v0.y + v0.z * v0.z + v0.w * v0.w
            + v1.x * v1.x + v1.y * v1.y + v1.z * v1.z + v1.w * v1.w;
    #pragma unroll
    for (int o = 16; o > 0; o >>= 1) s += __shfl_xor_sync(0xffffffffu, s, o);
    float inv = 1.0f / fmaxf(sqrtf(s), 1e-12f);

    __half2 hp[4];
    hp[0] = __halves2half2(__float2half_rn(v0.x * inv), __float2half_rn(v0.y * inv));
    hp[1] = __halves2half2(__float2half_rn(v0.z * inv), __float2half_rn(v0.w * inv));
    hp[2] = __halves2half2(__float2half_rn(v1.x * inv), __float2half_rn(v1.y * inv));
    hp[3] = __halves2half2(__float2half_rn(v1.z * inv), __float2half_rn(v1.w * inv));

    // k = 8t + 2*jj : chunk = t>>3, ks = (t>>1)&3, khi = t&1
    int mt = row >> 7;
    int mfrag = (row >> 4) & 7;
    int chunk = t >> 3;
    int ks = (t >> 1) & 3;
    int reg = ((row >> 3) & 1) | ((t & 1) << 1);   // a0/a1/a2/a3 slot
    size_t fragIdx = (((size_t)(mt * NCHUNK + chunk) * NKS + ks) * 8 + mfrag);
    char* base = (char*)g_Ap + fragIdx * 512 + ((row & 7) << 2) * 16 + reg * 4;
    #pragma unroll
    for (int jj = 0; jj < 4; jj++)
        *(__half2*)(base + jj * 16) = hp[jj];
}

// features -> fragment-ordered g_Bp. One thread per (unit, lane) 16B output.
__global__ void prepB_kernel(const float* __restrict__ f, int N) {
    long id = (long)blockIdx.x * blockDim.x + threadIdx.x;  // < NT*128*32
    int lane = (int)(id & 31);
    long unit = id >> 5;
    int nfp = (int)(unit & 7);
    int ks = (int)((unit >> 3) & 3);
    int c  = (int)((unit >> 5) & 3);
    int nt = (int)(unit >> 7);

    int n0 = nt * BN + nfp * 16 + (lane >> 2);
    int k0 = c * 64 + ks * 16 + (lane & 3) * 2;

    uint4 u;
    __half2* up = (__half2*)&u;
    __half2 z = __halves2half2(__float2half(0.f), __float2half(0.f));
    if (n0 < N) {
        float2 p0 = *(const float2*)(f + (size_t)n0 * KDIM + k0);
        float2 p1 = *(const float2*)(f + (size_t)n0 * KDIM + k0 + 8);
        up[0] = __halves2half2(__float2half_rn(p0.x), __float2half_rn(p0.y));
        up[1] = __halves2half2(__float2half_rn(p1.x), __float2half_rn(p1.y));
    } else { up[0] = z; up[1] = z; }
    if (n0 + 8 < N) {
        float2 p2 = *(const float2*)(f + (size_t)(n0 + 8) * KDIM + k0);
        float2 p3 = *(const float2*)(f + (size_t)(n0 + 8) * KDIM + k0 + 8);
        up[2] = __halves2half2(__float2half_rn(p2.x), __float2half_rn(p2.y));
        up[3] = __halves2half2(__float2half_rn(p3.x), __float2half_rn(p3.y));
    } else { up[2] = z; up[3] = z; }

    g_Bp[id] = u;
}

// ------------------------------ GEMM kernel -------------------------------

__global__ __launch_bounds__(256, 2)
void gemm_mma(float* __restrict__ C, int N,
              const float* __restrict__ feats, float* __restrict__ fcopy,
              long copy4_total) {
    const int tid = threadIdx.x;
    const int lane = tid & 31;
    const int wid = tid >> 5;
    const int mt = blockIdx.x;           // m fastest -> B tile L2/L1D reuse
    const int nt = blockIdx.y;
    const int m0 = mt * BM;
    const int n0 = nt * BN;
    const int am = (wid & 1) * 64;       // warp m-offset
    const int bn = (wid >> 1) * 32;      // warp n-offset

    // Fragment base pointers for (chunk=0, ks=0); step per it(=c*4+ks) is 256.
    const uint4* __restrict__ Ap =
        g_Ap + ((size_t)mt * NCHUNK * NKS * 8 + (wid & 1) * 4) * 32 + lane;
    const uint4* __restrict__ Bp =
        g_Bp + ((size_t)nt * NCHUNK * NKS * 8 + (wid >> 1) * 2) * 32 + lane;

    // fused passthrough copy: this CTA's slice of features -> fcopy.
    {
        long base = (long)(nt * gridDim.x + mt) * 1024;
        const float4* src = (const float4*)feats;
        float4* dst = (float4*)fcopy;
        #pragma unroll
        for (int it = 0; it < 4; it++) {
            long idx = base + it * 256 + tid;
            if (idx < copy4_total) dst[idx] = src[idx];
        }
    }

    float acc[4][4][4];
    #pragma unroll
    for (int mtt = 0; mtt < 4; mtt++)
        #pragma unroll
        for (int ntt = 0; ntt < 4; ntt++)
            #pragma unroll
            for (int e = 0; e < 4; e++) acc[mtt][ntt][e] = 0.0f;

    // Register double-buffered fragment pipeline over 16 k-steps.
    uint4 a[2][4], b[2][2];
    #pragma unroll
    for (int m = 0; m < 4; m++) a[0][m] = Ap[m * 32];
    #pragma unroll
    for (int p = 0; p < 2; p++) b[0][p] = Bp[p * 32];

    #pragma unroll
    for (int it = 0; it < NCHUNK * NKS; it++) {
        const int cur = it & 1, nx = cur ^ 1;
        if (it < NCHUNK * NKS - 1) {
            const int o = (it + 1) * 256;
            #pragma unroll
            for (int m = 0; m < 4; m++) a[nx][m] = Ap[o + m * 32];
            #pragma unroll
            for (int p = 0; p < 2; p++) b[nx][p] = Bp[o + p * 32];
        }
        #pragma unroll
        for (int mtt = 0; mtt < 4; mtt++) {
            #pragma unroll
            for (int ntt = 0; ntt < 4; ntt++) {
                const uint4& bu = b[cur][ntt >> 1];
                if (ntt & 1) { MMA(acc[mtt][ntt], a[cur][mtt], bu.z, bu.w); }
                else         { MMA(acc[mtt][ntt], a[cur][mtt], bu.x, bu.y); }
            }
        }
    }

    // ---- epilogue: direct stores (fp32) ----
    const int r0 = lane >> 2;
    const int cq = (lane & 3) * 2;
    #pragma unroll
    for (int mtt = 0; mtt < 4; mtt++) {
        #pragma unroll
        for (int ntt = 0; ntt < 4; ntt++) {
            int row = m0 + am + mtt * 16 + r0;
            int col = n0 + bn + ntt * 8 + cq;
            if (col < N) {
                float2 v0 = make_float2(acc[mtt][ntt][0], acc[mtt][ntt][1]);
                float2 v1 = make_float2(acc[mtt][ntt][2], acc[mtt][ntt][3]);
                *(float2*)&C[(size_t)row * N + col] = v0;
                *(float2*)&C[(size_t)(row + 8) * N + col] = v1;
            }
        }
    }
}

// ------------------------------ host side ---------------------------------

extern "C" void kernel_launch(void* const* d_in, const int* in_sizes, int n_in,
                              void* d_out, int out_size) {
    const float* x     = (const float*)d_in[0];   // [B, D]
    const float* feats = (const float*)d_in[2];   // [N, D]

    const int Bm = in_sizes[1];            // 2048
    const int D  = in_sizes[0] / Bm;       // 256
    const int N  = in_sizes[2] / D;        // 100000

    float* out = (float*)d_out;
    const size_t featE = (size_t)in_sizes[2];
    const size_t out_off = (size_t)out_size - featE;

    // 1) prep: normalize+fragment A, fragment B
    normA_kernel<<<Bm / 8, 256>>>(x);
    long bthreads = (long)NT * 128 * 32;   // one per 16B unit-lane
    prepB_kernel<<<(unsigned)((bthreads + 255) / 256), 256>>>(feats, N);

    // 2) GEMM (no dynamic smem) + fused passthrough copy
    long copy4_total = (long)featE / 4;
    dim3 grid(Bm / BM, (N + BN - 1) / BN);   // m fastest for B reuse
    gemm_mma<<<grid, 256>>>(out, N, feats, out + out_off, copy4_total);
}

// round 14
// speedup vs baseline: 1.1555x; 1.1555x over previous
#include <cuda_runtime.h>
#include <cuda_fp16.h>
#include <stdint.h>
#include <stddef.h>

// ---------------------------------------------------------------------------
// out0 = normalize_rows(x) @ features^T   [2048 x 100000]  (fp32)
// out1 = features (passthrough)           [100000 x 256]
// Round 13: R10 pipeline (3-stage cp.async.bulk, fused copy) with 4 warps of
// 64x64 per 128x128 tile (128 threads, 2 CTAs/SM, <=256 regs) to cut LDSM
// smem-port traffic by 33% -- the measured co-saturation bottleneck.
// ---------------------------------------------------------------------------

#define MROWS 2048
#define KDIM  256
#define NPAD  100096      // 782 * 128

#define BM 128
#define BN 128
#define BK 64
#define NCHUNK 4          // K / BK

#define TILE_BYTES 16384  // [128 rows][64 fp16] swizzled block
#define STAGE 32768       // A block + B block
#define OFF_MBAR 98304
#define SMEM_TOTAL (98304 + 128)

// Tiled+swizzled scratch: block (tile, chunk) is contiguous 16KB.
__device__ __align__(1024) __half g_At[MROWS * KDIM];
__device__ __align__(1024) __half g_Bt[(size_t)NPAD * KDIM];

// ------------------------------ helpers -----------------------------------

__device__ __forceinline__ uint32_t smem_u32(const void* p) {
    uint32_t a;
    asm("{ .reg .u64 t; cvta.to.shared.u64 t, %1; cvt.u32.u64 %0, t; }"
        : "=r"(a) : "l"(p));
    return a;
}

__device__ __forceinline__ void mbar_init(uint32_t mbar, uint32_t cnt) {
    asm volatile("mbarrier.init.shared.b64 [%0], %1;" :: "r"(mbar), "r"(cnt) : "memory");
}
__device__ __forceinline__ void mbar_expect_tx(uint32_t mbar, uint32_t bytes) {
    asm volatile("mbarrier.arrive.expect_tx.shared.b64 _, [%0], %1;"
                 :: "r"(mbar), "r"(bytes) : "memory");
}
__device__ __forceinline__ void mbar_wait(uint32_t mbar, uint32_t parity) {
    asm volatile(
        "{\n\t.reg .pred P;\n"
        "WL_%=:\n\t"
        "mbarrier.try_wait.parity.acquire.cta.shared::cta.b64 P, [%0], %1, 0x989680;\n\t"
        "@P bra WD_%=;\n\t"
        "bra WL_%=;\n"
        "WD_%=:\n\t}"
        :: "r"(mbar), "r"(parity) : "memory");
}

// 1D bulk copy global -> shared::cta with mbarrier completion (sm_90 base).
__device__ __forceinline__ void bulk_ld(uint32_t dst, const void* src,
                                        uint32_t bytes, uint32_t mbar) {
    asm volatile(
        "cp.async.bulk.shared::cta.global.mbarrier::complete_tx::bytes "
        "[%0], [%1], %2, [%3];"
        :: "r"(dst), "l"(src), "r"(bytes), "r"(mbar) : "memory");
}

__device__ __forceinline__ void ldmx4(uint32_t* f, uint32_t addr) {
    asm volatile("ldmatrix.sync.aligned.m8n8.x4.shared.b16 {%0,%1,%2,%3}, [%4];"
                 : "=r"(f[0]), "=r"(f[1]), "=r"(f[2]), "=r"(f[3]) : "r"(addr));
}

#define MMA(c, a, b0v, b1v)                                                   \
    asm volatile(                                                             \
        "mma.sync.aligned.m16n8k16.row.col.f32.f16.f16.f32 "                  \
        "{%0,%1,%2,%3},{%4,%5,%6,%7},{%8,%9},{%0,%1,%2,%3};"                  \
        : "+f"((c)[0]), "+f"((c)[1]), "+f"((c)[2]), "+f"((c)[3])              \
        : "r"((a)[0]), "r"((a)[1]), "r"((a)[2]), "r"((a)[3]),                 \
          "r"(b0v), "r"(b1v))

// Swizzled byte offset for 16B-unit (r, u) in a [128][64] fp16 tile (128B rows).
__device__ __host__ __forceinline__ uint32_t swz(int r, int u) {
    return (uint32_t)(r * 128 + ((u ^ (r & 7)) << 4));
}

// --------------------------- prep kernels ---------------------------------

// One warp per row: normalize + fp16 convert + write into tiled/swizzled g_At.
__global__ void normalize_h_kernel(const float* __restrict__ x) {
    int row = blockIdx.x * 8 + ((int)threadIdx.x >> 5);
    int t = threadIdx.x & 31;               // 0..31, each owns 8 floats
    const float4* xr = (const float4*)(x + (size_t)row * KDIM);
    float4 v0 = xr[2 * t], v1 = xr[2 * t + 1];
    float s = v0.x * v0.x + v0.y * v0.y + v0.z * v0.z + v0.w * v0.w
            + v1.x * v1.x + v1.y * v1.y + v1.z * v1.z + v1.w * v1.w;
    #pragma unroll
    for (int o = 16; o > 0; o >>= 1) s += __shfl_xor_sync(0xffffffffu, s, o);
    float inv = 1.0f / fmaxf(sqrtf(s), 1e-12f);

    uint32_t h[4];
    __half2* hp = (__half2*)h;
    hp[0] = __halves2half2(__float2half_rn(v0.x * inv), __float2half_rn(v0.y * inv));
    hp[1] = __halves2half2(__float2half_rn(v0.z * inv), __float2half_rn(v0.w * inv));
    hp[2] = __halves2half2(__float2half_rn(v1.x * inv), __float2half_rn(v1.y * inv));
    hp[3] = __halves2half2(__float2half_rn(v1.z * inv), __float2half_rn(v1.w * inv));

    int k0 = t * 8;
    int blk = (row >> 7) * NCHUNK + (k0 >> 6);
    uint32_t off = (uint32_t)blk * TILE_BYTES + swz(row & 127, (k0 & 63) >> 3);
    *(uint4*)((char*)g_At + off) = *(uint4*)h;
}

// features -> fp16 tiled/swizzled g_Bt; zero pad rows.
__global__ void feat_h_kernel(const float* __restrict__ f, int N) {
    long i = (long)blockIdx.x * blockDim.x + threadIdx.x;   // < NPAD*32
    int n = (int)(i >> 5);
    int j = (int)(i & 31);
    int k0 = j * 8;

    uint32_t h[4];
    if (n < N) {
        const float4* fr = (const float4*)(f + (size_t)n * KDIM + k0);
        float4 v0 = fr[0], v1 = fr[1];
        __half2* hp = (__half2*)h;
        hp[0] = __halves2half2(__float2half_rn(v0.x), __float2half_rn(v0.y));
        hp[1] = __halves2half2(__float2half_rn(v0.z), __float2half_rn(v0.w));
        hp[2] = __halves2half2(__float2half_rn(v1.x), __float2half_rn(v1.y));
        hp[3] = __halves2half2(__float2half_rn(v1.z), __float2half_rn(v1.w));
    } else {
        h[0] = h[1] = h[2] = h[3] = 0u;
    }
    int blk = (n >> 7) * NCHUNK + (k0 >> 6);
    uint32_t off_in = swz(n & 127, (k0 & 63) >> 3);
    *(uint4*)((char*)g_Bt + (size_t)blk * TILE_BYTES + off_in) = *(uint4*)h;
}

// ------------------------------ GEMM kernel -------------------------------
// 128 threads = 4 warps, each computing a 64x64 sub-tile of the 128x128 tile.

__global__ __launch_bounds__(128, 2)
void gemm_mma(float* __restrict__ C, int N,
              const float* __restrict__ feats, float* __restrict__ fcopy,
              long copy4_total) {
    extern __shared__ __align__(128) char smem[];
    uint32_t sb = smem_u32(smem);

    const int tid = threadIdx.x;
    const int lane = tid & 31;
    const int wid = tid >> 5;            // 0..3
    const int mt = blockIdx.x;           // m fastest -> B tile L2 reuse
    const int nt = blockIdx.y;
    const int m0 = mt * BM;
    const int n0 = nt * BN;
    const int am = (wid & 1) * 64;       // warp m-offset
    const int bn = (wid >> 1) * 64;      // warp n-offset
    const int lr = lane & 7;
    const int q  = lane >> 3;

    const char* gA = (const char*)g_At + (size_t)mt * NCHUNK * TILE_BYTES;
    const char* gB = (const char*)g_Bt + (size_t)nt * NCHUNK * TILE_BYTES;

    const uint32_t full0 = sb + OFF_MBAR;

    if (tid == 0) {
        mbar_init(full0, 1);
        mbar_init(full0 + 8, 1);
        mbar_init(full0 + 16, 1);
    }
    __syncthreads();

    // prologue: chunks 0,1,2 into stages 0,1,2
    if (tid == 0) {
        #pragma unroll
        for (int c = 0; c < 3; c++) {
            uint32_t fb = full0 + 8 * c;
            uint32_t st = sb + c * STAGE;
            mbar_expect_tx(fb, STAGE);
            bulk_ld(st,              gA + c * TILE_BYTES, TILE_BYTES, fb);
            bulk_ld(st + TILE_BYTES, gB + c * TILE_BYTES, TILE_BYTES, fb);
        }
    }

    // fused passthrough copy: this CTA's slice of features -> fcopy.
    {
        long base = (long)(nt * gridDim.x + mt) * 1024;
        const float4* src = (const float4*)feats;
        float4* dst = (float4*)fcopy;
        #pragma unroll
        for (int it = 0; it < 8; it++) {
            long idx = base + it * 128 + tid;
            if (idx < copy4_total) dst[idx] = src[idx];
        }
    }

    float acc[4][8][4];
    #pragma unroll
    for (int mtt = 0; mtt < 4; mtt++)
        #pragma unroll
        for (int ntt = 0; ntt < 8; ntt++)
            #pragma unroll
            for (int e = 0; e < 4; e++) acc[mtt][ntt][e] = 0.0f;

    #pragma unroll
    for (int c = 0; c < NCHUNK; c++) {
        const int s = c % 3;
        mbar_wait(full0 + 8 * s, (c >= 3) ? 1 : 0);

        uint32_t st = sb + s * STAGE;
        uint32_t sA = st, sB = st + TILE_BYTES;

        #pragma unroll
        for (int ks = 0; ks < 4; ks++) {
            uint32_t aF[4][4];
            #pragma unroll
            for (int mtt = 0; mtt < 4; mtt++) {
                int r = am + mtt * 16 + ((q & 1) << 3) + lr;
                int u = ks * 2 + (q >> 1);
                ldmx4(aF[mtt], sA + swz(r, u));
            }
            uint32_t bF[4][4];
            #pragma unroll
            for (int np = 0; np < 4; np++) {
                int r = bn + np * 16 + ((q >> 1) << 3) + lr;
                int u = ks * 2 + (q & 1);
                ldmx4(bF[np], sB + swz(r, u));
            }
            #pragma unroll
            for (int mtt = 0; mtt < 4; mtt++) {
                #pragma unroll
                for (int ntt = 0; ntt < 8; ntt++) {
                    const uint32_t* bu = bF[ntt >> 1];
                    if (ntt & 1) { MMA(acc[mtt][ntt], aF[mtt], bu[2], bu[3]); }
                    else         { MMA(acc[mtt][ntt], aF[mtt], bu[0], bu[1]); }
                }
            }
        }

        // After chunk 0: stage 0 is free; load chunk 3 into it.
        if (c == 0) {
            __syncthreads();            // all warps done reading stage 0
            if (tid == 0) {
                mbar_expect_tx(full0, STAGE);
                bulk_ld(st,              gA + 3 * TILE_BYTES, TILE_BYTES, full0);
                bulk_ld(st + TILE_BYTES, gB + 3 * TILE_BYTES, TILE_BYTES, full0);
            }
        }
    }

    // ---- epilogue: direct stores (fp32) ----
    const int r0 = lane >> 2;
    const int cq = (lane & 3) * 2;
    #pragma unroll
    for (int mtt = 0; mtt < 4; mtt++) {
        #pragma unroll
        for (int ntt = 0; ntt < 8; ntt++) {
            int row = m0 + am + mtt * 16 + r0;
            int col = n0 + bn + ntt * 8 + cq;
            if (col < N) {
                float2 v0 = make_float2(acc[mtt][ntt][0], acc[mtt][ntt][1]);
                float2 v1 = make_float2(acc[mtt][ntt][2], acc[mtt][ntt][3]);
                *(float2*)&C[(size_t)row * N + col] = v0;
                *(float2*)&C[(size_t)(row + 8) * N + col] = v1;
            }
        }
    }
}

// ------------------------------ host side ---------------------------------

extern "C" void kernel_launch(void* const* d_in, const int* in_sizes, int n_in,
                              void* d_out, int out_size) {
    const float* x     = (const float*)d_in[0];   // [B, D]
    const float* feats = (const float*)d_in[2];   // [N, D]

    const int Bm = in_sizes[1];            // 2048
    const int D  = in_sizes[0] / Bm;       // 256
    const int N  = in_sizes[2] / D;        // 100000

    float* out = (float*)d_out;
    const size_t featE = (size_t)in_sizes[2];
    const size_t out_off = (size_t)out_size - featE;

    // 1) prep: normalize A -> tiled fp16, B -> tiled fp16
    normalize_h_kernel<<<Bm / 8, 256>>>(x);
    long units = (long)NPAD * 32;          // 16B units in g_Bt
    feat_h_kernel<<<(unsigned)((units + 255) / 256), 256>>>(feats, N);

    // 2) GEMM + fused passthrough copy
    static int smem_set = 0;
    if (!smem_set) {
        cudaFuncSetAttribute(gemm_mma, cudaFuncAttributeMaxDynamicSharedMemorySize,
                             SMEM_TOTAL);
        smem_set = 1;
    }
    long copy4_total = (long)featE / 4;
    dim3 grid(Bm / BM, (N + BN - 1) / BN);   // m fastest for B-tile L2 reuse
    gemm_mma<<<grid, 128, SMEM_TOTAL>>>(out, N, feats, out + out_off, copy4_total);
}